// round 2
// baseline (speedup 1.0000x reference)
#include <cuda_runtime.h>
#include <math.h>

// Lin2d: x <- x @ Mt, 1000 times, Mt = [[c,-s],[s,c]] (float32 c,s).
// Complex form: z = x0 + i*x1, one step z -> (c - i*s) * z.
// 1000 steps == multiply by w = (c - i*s)^1000, computed on host in double.
// Kernel applies the single 2x2 transform: pure streaming, HBM-bound.

__global__ void lin2d_apply_kernel(const float4* __restrict__ in,
                                   float4* __restrict__ out,
                                   int n4, float wr, float wi) {
    int i = blockIdx.x * blockDim.x + threadIdx.x;
    if (i >= n4) return;
    float4 v = in[i];
    // v = (x0, y0, x1, y1): two 2-d states per float4
    float4 r;
    r.x = fmaf(wr, v.x, -wi * v.y);
    r.y = fmaf(wi, v.x,  wr * v.y);
    r.z = fmaf(wr, v.z, -wi * v.w);
    r.w = fmaf(wi, v.z,  wr * v.w);
    out[i] = r;
}

extern "C" void kernel_launch(void* const* d_in, const int* in_sizes, int n_in,
                              void* d_out, int out_size) {
    const float* x = (const float*)d_in[0];
    float* y = (float*)d_out;
    const int n = in_sizes[0];       // total floats = BATCH*2 (multiple of 4)
    const int n4 = n / 4;

    // Host-side constant computation (runs at capture; deterministic pure math).
    const double theta = 3.14159265358979323846 / 100.0;
    // Match numpy: double cos/sin rounded to float32, then promoted.
    const double c = (double)((float)cos(theta));
    const double s = (double)((float)sin(theta));
    const int N = 1000;
    const double r   = hypot(c, s);
    const double phi = atan2(s, c);
    const double mag = pow(r, (double)N);
    // w = (c - i*s)^N = mag * (cos(N*phi) - i*sin(N*phi))
    const float wr = (float)(mag * cos((double)N * phi));
    const float wi = (float)(-mag * sin((double)N * phi));

    const int threads = 256;
    const int blocks = (n4 + threads - 1) / threads;
    lin2d_apply_kernel<<<blocks, threads>>>((const float4*)x, (float4*)y,
                                            n4, wr, wi);
}